// round 10
// baseline (speedup 1.0000x reference)
#include <cuda_runtime.h>

// Problem constants
#define NN   1024
#define PP   4
#define SS   12
#define MM   64
#define KK   16
#define MK   80
#define NSYM 13
#define NBLK (NN*PP)              // 4096
#define BLKS_PER_CTA 4
#define NTHREADS (BLKS_PER_CTA*NSYM*8)   // 416 = 13 warps exactly

// Output layout: [info_pilot | info_sig | H_true | noise_pwr]
#define IP_OFF 0
#define IS_OFF (NN*PP*MM*2)                  //   524288
#define HT_OFF (IS_OFF + NN*PP*SS*MM*2)      //  6815744
#define NP_OFF (HT_OFF + NN*PP*MM*2)         //  7340032

#define NOISE_PWR 1.5625e-4f                 // 1/(64*10^2)
#define CNOISE 8.8388347648e-3f              // sqrt(noise_pwr/2)
#define SQ2H 0.70710678f

// W64^j for j = 0..7  (higher powers via log-depth chain)
__constant__ float2 c_W8[8] = {
    { 1.00000000f,  0.00000000f}, { 0.99518473f, -0.09801714f},
    { 0.98078528f, -0.19509032f}, { 0.95694034f, -0.29028468f},
    { 0.92387953f, -0.38268343f}, { 0.88192126f, -0.47139674f},
    { 0.83146961f, -0.55557023f}, { 0.77301045f, -0.63439328f}
};

// amp[l] = sqrt(0.5 * exp(-l/4) / sum_l exp(-l/4))
__constant__ float c_amp[8] = {
    0.35764563f, 0.31562116f, 0.27853470f, 0.24580602f,
    0.21692305f, 0.19143393f, 0.16893985f, 0.14908891f
};

__device__ __forceinline__ float2 cadd(float2 a, float2 b) { return make_float2(a.x+b.x, a.y+b.y); }
__device__ __forceinline__ float2 csub(float2 a, float2 b) { return make_float2(a.x-b.x, a.y-b.y); }
__device__ __forceinline__ float2 mul_mi(float2 z) { return make_float2(z.y, -z.x); }   // -i*z
__device__ __forceinline__ float2 cmul(float2 a, float2 b) {
    return make_float2(fmaf(a.x, b.x, -a.y*b.y), fmaf(a.x, b.y, a.y*b.x));
}
__device__ __forceinline__ float2 w81(float2 z) { return make_float2(SQ2H*(z.x+z.y), SQ2H*(z.y-z.x)); }
__device__ __forceinline__ float2 w83(float2 z) { return make_float2(SQ2H*(z.y-z.x), -SQ2H*(z.x+z.y)); }

// X[k] = sum_n x[n] * W8^{nk}  (radix-2 DIT)
__device__ __forceinline__ void dft8(const float2* x, float2* X) {
    float2 t0 = cadd(x[0], x[4]), t1 = csub(x[0], x[4]);
    float2 t2 = cadd(x[2], x[6]), t3 = csub(x[2], x[6]);
    float2 E0 = cadd(t0, t2), E2 = csub(t0, t2);
    float2 mt3 = mul_mi(t3);
    float2 E1 = cadd(t1, mt3), E3 = csub(t1, mt3);

    float2 s0 = cadd(x[1], x[5]), s1 = csub(x[1], x[5]);
    float2 s2 = cadd(x[3], x[7]), s3 = csub(x[3], x[7]);
    float2 O0 = cadd(s0, s2), O2 = csub(s0, s2);
    float2 ms3 = mul_mi(s3);
    float2 O1 = cadd(s1, ms3), O3 = csub(s1, ms3);

    float2 o1 = w81(O1);
    float2 o2 = mul_mi(O2);
    float2 o3 = w83(O3);

    X[0] = cadd(E0, O0); X[4] = csub(E0, O0);
    X[1] = cadd(E1, o1); X[5] = csub(E1, o1);
    X[2] = cadd(E2, o2); X[6] = csub(E2, o2);
    X[3] = cadd(E3, o3); X[7] = csub(E3, o3);
}

__global__ __launch_bounds__(NTHREADS, 3) void ofdm_fused(
    const float* __restrict__ x,
    const float* __restrict__ pilot_raw,
    const float* __restrict__ cof_unit,
    const float* __restrict__ noise_unit,
    float* __restrict__ out)
{
    __shared__ float2 Z[BLKS_PER_CTA*NSYM][8][9];   // padded transpose buffer
    __shared__ float2 sH[BLKS_PER_CTA][64];          // deduped channel response

    const int tid  = threadIdx.x;
    const int grp  = tid >> 3;                // 0..51
    const int lb   = tid & 7;
    const int blkL = grp / NSYM;              // 0..3
    const int sym  = grp - blkL * NSYM;       // 0..12
    const int blk  = blockIdx.x * BLKS_PER_CTA + blkL;
    const bool isp = (sym == 0);
    // 8-lane group mask: exactly the lanes that share this thread's isp value
    const unsigned gmask = 0xFFu << ((tid & 31) & ~7);

    // ---- noise loads (post-CP samples only), issued first for MLP ----
    const float2* nb = (const float2*)noise_unit
                     + (size_t)blk * NSYM * MK + sym * MK + KK + lb;
    float2 in[8];
    #pragma unroll
    for (int a = 0; a < 8; a++) in[a] = nb[a * 8];

    // ---- powers p[c] = W64^{lb*c}, log-depth chain from one constant ----
    float2 p1 = c_W8[lb];
    float2 p2 = cmul(p1, p1);
    float2 p3 = cmul(p2, p1);
    float2 p4 = cmul(p2, p2);
    float2 p5 = cmul(p4, p1);
    float2 p6 = cmul(p3, p3);
    float2 p7 = cmul(p4, p3);

    // ---- noise FFT64 stage 1: DFT8 over a, then twiddle W64^{lb*c} ----
    {
        float2 u[8];
        dft8(in, u);
        u[1] = cmul(u[1], p1); u[2] = cmul(u[2], p2); u[3] = cmul(u[3], p3);
        u[4] = cmul(u[4], p4); u[5] = cmul(u[5], p5); u[6] = cmul(u[6], p6);
        u[7] = cmul(u[7], p7);
        #pragma unroll
        for (int c = 0; c < 8; c++) Z[grp][lb][c] = u[c];
    }

    // ---- H computed ONCE per blk, by the sym-0 group only ----
    if (isp) {
        const float4* cp4 = (const float4*)((const float2*)cof_unit + blk * 8);
        float4 q0 = cp4[0], q1 = cp4[1], q2 = cp4[2], q3 = cp4[3];
        float2 e[8];
        e[0] = make_float2(c_amp[0]*q0.x, c_amp[0]*q0.y);
        e[1] = cmul(make_float2(c_amp[1]*q0.z, c_amp[1]*q0.w), p1);
        e[2] = cmul(make_float2(c_amp[2]*q1.x, c_amp[2]*q1.y), p2);
        e[3] = cmul(make_float2(c_amp[3]*q1.z, c_amp[3]*q1.w), p3);
        e[4] = cmul(make_float2(c_amp[4]*q2.x, c_amp[4]*q2.y), p4);
        e[5] = cmul(make_float2(c_amp[5]*q2.z, c_amp[5]*q2.w), p5);
        e[6] = cmul(make_float2(c_amp[6]*q3.x, c_amp[6]*q3.y), p6);
        e[7] = cmul(make_float2(c_amp[7]*q3.z, c_amp[7]*q3.w), p7);
        float2 Hv[8];
        dft8(e, Hv);                          // Hv[d] = H[lb + 8d]
        float2* hq = (float2*)(out + HT_OFF) + blk * 64;
        #pragma unroll
        for (int d = 0; d < 8; d++) {
            sH[blkL][lb + 8 * d] = Hv[d];
            hq[lb + 8 * d] = Hv[d];
        }
    }
    if (tid == 0 && blockIdx.x == 0) out[NP_OFF] = NOISE_PWR;

    // ---- signal loads overlap the barrier ----
    const float2* sp = isp ? ((const float2*)pilot_raw + blk * 64)
                           : ((const float2*)x + ((size_t)blk * SS + (sym - 1)) * 64);
    float2 sv[8];
    #pragma unroll
    for (int d = 0; d < 8; d++) sv[d] = sp[lb + 8 * d];

    __syncthreads();   // publishes Z (transpose) and sH

    if (isp) {
        // group-local reduction: mask matches exactly the executing lanes
        float pw = 0.f;
        #pragma unroll
        for (int d = 0; d < 8; d++) pw += sv[d].x * sv[d].x + sv[d].y * sv[d].y;
        pw += __shfl_xor_sync(gmask, pw, 1);
        pw += __shfl_xor_sync(gmask, pw, 2);
        pw += __shfl_xor_sync(gmask, pw, 4);
        float scale = 8.0f * rsqrtf(pw);      // sqrt(PWR/2)/sqrt(mean(pilot_raw^2))
        #pragma unroll
        for (int d = 0; d < 8; d++) { sv[d].x *= scale; sv[d].y *= scale; }
    }

    // ---- fold H*sig in place (H from smem, mostly broadcast reads) ----
    #pragma unroll
    for (int d = 0; d < 8; d++) sv[d] = cmul(sH[blkL][lb + 8 * d], sv[d]);

    // ---- transpose read + stage 2 ----
    float2 z[8];
    #pragma unroll
    for (int b = 0; b < 8; b++) z[b] = Z[grp][b][lb];
    float2 Nf[8];
    dft8(z, Nf);                              // Nf[d] = N[lb + 8d]

    // ---- epilogue: out = (H*sig) + CNOISE * noiseFFT ----
    float2* op = isp ? ((float2*)(out + IP_OFF) + blk * 64)
                     : ((float2*)(out + IS_OFF) + ((size_t)blk * SS + (sym - 1)) * 64);
    #pragma unroll
    for (int d = 0; d < 8; d++) {
        float2 r;
        r.x = fmaf(CNOISE, Nf[d].x, sv[d].x);
        r.y = fmaf(CNOISE, Nf[d].y, sv[d].y);
        op[lb + 8 * d] = r;
    }
}

extern "C" void kernel_launch(void* const* d_in, const int* in_sizes, int n_in,
                              void* d_out, int out_size) {
    const float* x          = (const float*)d_in[0];
    const float* pilot_raw  = (const float*)d_in[1];
    const float* cof_unit   = (const float*)d_in[2];
    const float* noise_unit = (const float*)d_in[3];
    float* out = (float*)d_out;

    ofdm_fused<<<NBLK / BLKS_PER_CTA, NTHREADS>>>(x, pilot_raw, cof_unit, noise_unit, out);
}

// round 11
// speedup vs baseline: 1.1153x; 1.1153x over previous
#include <cuda_runtime.h>

// Problem constants
#define NN   1024
#define PP   4
#define SS   12
#define MM   64
#define KK   16
#define MK   80
#define NSYM 13
#define NBLK (NN*PP)              // 4096
#define NSYMTOT (NBLK*NSYM)       // 53248

// Output layout: [info_pilot | info_sig | H_true | noise_pwr]
#define IP_OFF 0
#define IS_OFF (NN*PP*MM*2)                  //   524288
#define HT_OFF (IS_OFF + NN*PP*SS*MM*2)      //  6815744
#define NP_OFF (HT_OFF + NN*PP*MM*2)         //  7340032

#define NOISE_PWR 1.5625e-4f                 // 1/(64*10^2)
#define CNOISE 8.8388347648e-3f              // sqrt(noise_pwr/2)
#define SQ2H 0.70710678f

// W64^j for j = 0..7  (higher powers via log-depth chain)
__constant__ float2 c_W8[8] = {
    { 1.00000000f,  0.00000000f}, { 0.99518473f, -0.09801714f},
    { 0.98078528f, -0.19509032f}, { 0.95694034f, -0.29028468f},
    { 0.92387953f, -0.38268343f}, { 0.88192126f, -0.47139674f},
    { 0.83146961f, -0.55557023f}, { 0.77301045f, -0.63439328f}
};

// amp[l] = sqrt(0.5 * exp(-l/4) / sum_l exp(-l/4))
__constant__ float c_amp[8] = {
    0.35764563f, 0.31562116f, 0.27853470f, 0.24580602f,
    0.21692305f, 0.19143393f, 0.16893985f, 0.14908891f
};

__device__ __forceinline__ float2 cadd(float2 a, float2 b) { return make_float2(a.x+b.x, a.y+b.y); }
__device__ __forceinline__ float2 csub(float2 a, float2 b) { return make_float2(a.x-b.x, a.y-b.y); }
__device__ __forceinline__ float2 mul_mi(float2 z) { return make_float2(z.y, -z.x); }   // -i*z
__device__ __forceinline__ float2 cmul(float2 a, float2 b) {
    return make_float2(fmaf(a.x, b.x, -a.y*b.y), fmaf(a.x, b.y, a.y*b.x));
}
__device__ __forceinline__ float2 w81(float2 z) { return make_float2(SQ2H*(z.x+z.y), SQ2H*(z.y-z.x)); }
__device__ __forceinline__ float2 w83(float2 z) { return make_float2(SQ2H*(z.y-z.x), -SQ2H*(z.x+z.y)); }

// X[k] = sum_n x[n] * W8^{nk}  (radix-2 DIT)
__device__ __forceinline__ void dft8(const float2* x, float2* X) {
    float2 t0 = cadd(x[0], x[4]), t1 = csub(x[0], x[4]);
    float2 t2 = cadd(x[2], x[6]), t3 = csub(x[2], x[6]);
    float2 E0 = cadd(t0, t2), E2 = csub(t0, t2);
    float2 mt3 = mul_mi(t3);
    float2 E1 = cadd(t1, mt3), E3 = csub(t1, mt3);

    float2 s0 = cadd(x[1], x[5]), s1 = csub(x[1], x[5]);
    float2 s2 = cadd(x[3], x[7]), s3 = csub(x[3], x[7]);
    float2 O0 = cadd(s0, s2), O2 = csub(s0, s2);
    float2 ms3 = mul_mi(s3);
    float2 O1 = cadd(s1, ms3), O3 = csub(s1, ms3);

    float2 o1 = w81(O1);
    float2 o2 = mul_mi(O2);
    float2 o3 = w83(O3);

    X[0] = cadd(E0, O0); X[4] = csub(E0, O0);
    X[1] = cadd(E1, o1); X[5] = csub(E1, o1);
    X[2] = cadd(E2, o2); X[6] = csub(E2, o2);
    X[3] = cadd(E3, o3); X[7] = csub(E3, o3);
}

__global__ __launch_bounds__(128, 9) void ofdm_fused(
    const float* __restrict__ x,
    const float* __restrict__ pilot_raw,
    const float* __restrict__ cof_unit,
    const float* __restrict__ noise_unit,
    float* __restrict__ out)
{
    __shared__ float2 Z[16][8][9];            // padded transpose buffer

    const int tid  = threadIdx.x;
    const int g    = blockIdx.x * 128 + tid;
    const int gsym = g >> 3;                  // 0..53247
    const int lb   = g & 7;
    const int grp  = tid >> 3;
    const int blk  = gsym / NSYM;
    const int sym  = gsym - blk * NSYM;
    const bool isp = (sym == 0);
    // 8-lane group mask: exactly the lanes that share this thread's isp value
    const unsigned gmask = 0xFFu << ((tid & 31) & ~7);

    // ---- ALL streaming loads issued up front: 16 outstanding LDGs ----
    const float2* nb = (const float2*)noise_unit
                     + (size_t)blk * NSYM * MK + sym * MK + KK + lb;
    float2 in[8];
    #pragma unroll
    for (int a = 0; a < 8; a++) in[a] = nb[a * 8];

    const float2* sp = isp ? ((const float2*)pilot_raw + blk * 64)
                           : ((const float2*)x + ((size_t)blk * SS + (sym - 1)) * 64);
    float2 sv[8];
    #pragma unroll
    for (int d = 0; d < 8; d++) sv[d] = sp[lb + 8 * d];

    // ---- powers p[c] = W64^{lb*c}, log-depth chain from one constant ----
    float2 p1 = c_W8[lb];
    float2 p2 = cmul(p1, p1);
    float2 p3 = cmul(p2, p1);
    float2 p4 = cmul(p2, p2);
    float2 p5 = cmul(p4, p1);
    float2 p6 = cmul(p3, p3);
    float2 p7 = cmul(p4, p3);

    // ---- noise FFT64 stage 1: DFT8 over a, then twiddle W64^{lb*c} ----
    {
        float2 u[8];
        dft8(in, u);
        u[1] = cmul(u[1], p1); u[2] = cmul(u[2], p2); u[3] = cmul(u[3], p3);
        u[4] = cmul(u[4], p4); u[5] = cmul(u[5], p5); u[6] = cmul(u[6], p6);
        u[7] = cmul(u[7], p7);
        #pragma unroll
        for (int c = 0; c < 8; c++) Z[grp][lb][c] = u[c];
    }

    // ---- H in-thread: Hv[d] = DFT8_l( amp_l*cof_l*W64^{l*lb} ) ----
    float2 Hv[8];
    {
        const float4* cp4 = (const float4*)((const float2*)cof_unit + blk * 8);
        float4 q0 = cp4[0], q1 = cp4[1], q2 = cp4[2], q3 = cp4[3];
        float2 e[8];
        e[0] = make_float2(c_amp[0]*q0.x, c_amp[0]*q0.y);
        e[1] = cmul(make_float2(c_amp[1]*q0.z, c_amp[1]*q0.w), p1);
        e[2] = cmul(make_float2(c_amp[2]*q1.x, c_amp[2]*q1.y), p2);
        e[3] = cmul(make_float2(c_amp[3]*q1.z, c_amp[3]*q1.w), p3);
        e[4] = cmul(make_float2(c_amp[4]*q2.x, c_amp[4]*q2.y), p4);
        e[5] = cmul(make_float2(c_amp[5]*q2.z, c_amp[5]*q2.w), p5);
        e[6] = cmul(make_float2(c_amp[6]*q3.x, c_amp[6]*q3.y), p6);
        e[7] = cmul(make_float2(c_amp[7]*q3.z, c_amp[7]*q3.w), p7);
        dft8(e, Hv);                          // Hv[d] = H[lb + 8d]
    }

    // ---- sym-0 group stores H_true while it's live ----
    if (isp) {
        float2* hq = (float2*)(out + HT_OFF) + blk * 64;
        #pragma unroll
        for (int d = 0; d < 8; d++) hq[lb + 8 * d] = Hv[d];
    }
    if (g == 0) out[NP_OFF] = NOISE_PWR;

    if (isp) {
        // group-local reduction: mask matches exactly the executing lanes
        float pw = 0.f;
        #pragma unroll
        for (int d = 0; d < 8; d++) pw += sv[d].x * sv[d].x + sv[d].y * sv[d].y;
        pw += __shfl_xor_sync(gmask, pw, 1);
        pw += __shfl_xor_sync(gmask, pw, 2);
        pw += __shfl_xor_sync(gmask, pw, 4);
        float scale = 8.0f * rsqrtf(pw);      // sqrt(PWR/2)/sqrt(mean(pilot_raw^2))
        #pragma unroll
        for (int d = 0; d < 8; d++) { sv[d].x *= scale; sv[d].y *= scale; }
    }

    // ---- fold H*sig in place: Hv dies here, before Nf materializes ----
    #pragma unroll
    for (int d = 0; d < 8; d++) sv[d] = cmul(Hv[d], sv[d]);

    __syncwarp();

    // ---- transpose read + stage 2 ----
    float2 z[8];
    #pragma unroll
    for (int b = 0; b < 8; b++) z[b] = Z[grp][b][lb];
    float2 Nf[8];
    dft8(z, Nf);                              // Nf[d] = N[lb + 8d]

    // ---- epilogue: out = (H*sig) + CNOISE * noiseFFT ----
    float2* op = isp ? ((float2*)(out + IP_OFF) + blk * 64)
                     : ((float2*)(out + IS_OFF) + ((size_t)blk * SS + (sym - 1)) * 64);
    #pragma unroll
    for (int d = 0; d < 8; d++) {
        float2 r;
        r.x = fmaf(CNOISE, Nf[d].x, sv[d].x);
        r.y = fmaf(CNOISE, Nf[d].y, sv[d].y);
        op[lb + 8 * d] = r;
    }
}

extern "C" void kernel_launch(void* const* d_in, const int* in_sizes, int n_in,
                              void* d_out, int out_size) {
    const float* x          = (const float*)d_in[0];
    const float* pilot_raw  = (const float*)d_in[1];
    const float* cof_unit   = (const float*)d_in[2];
    const float* noise_unit = (const float*)d_in[3];
    float* out = (float*)d_out;

    ofdm_fused<<<NSYMTOT * 8 / 128, 128>>>(x, pilot_raw, cof_unit, noise_unit, out);
}

// round 12
// speedup vs baseline: 1.3341x; 1.1961x over previous
#include <cuda_runtime.h>

// Problem constants
#define NN   1024
#define PP   4
#define SS   12
#define MM   64
#define KK   16
#define MK   80
#define NSYM 13
#define NBLK (NN*PP)              // 4096
#define NSYMTOT (NBLK*NSYM)       // 53248

// Output layout: [info_pilot | info_sig | H_true | noise_pwr]
#define IP_OFF 0
#define IS_OFF (NN*PP*MM*2)                  //   524288
#define HT_OFF (IS_OFF + NN*PP*SS*MM*2)      //  6815744
#define NP_OFF (HT_OFF + NN*PP*MM*2)         //  7340032

#define NOISE_PWR 1.5625e-4f                 // 1/(64*10^2)
#define CNOISE 8.8388347648e-3f              // sqrt(noise_pwr/2)
#define SQ2H 0.70710678f

// W64^j for j = 0..7  (higher powers via log-depth chain)
__constant__ float2 c_W8[8] = {
    { 1.00000000f,  0.00000000f}, { 0.99518473f, -0.09801714f},
    { 0.98078528f, -0.19509032f}, { 0.95694034f, -0.29028468f},
    { 0.92387953f, -0.38268343f}, { 0.88192126f, -0.47139674f},
    { 0.83146961f, -0.55557023f}, { 0.77301045f, -0.63439328f}
};

// amp[l] = sqrt(0.5 * exp(-l/4) / sum_l exp(-l/4))
__constant__ float c_amp[8] = {
    0.35764563f, 0.31562116f, 0.27853470f, 0.24580602f,
    0.21692305f, 0.19143393f, 0.16893985f, 0.14908891f
};

// ---------- packed f32x2 helpers (Blackwell) ----------
typedef unsigned long long f2p;

__device__ __forceinline__ f2p pack2(float a, float b) {
    f2p r; asm("mov.b64 %0, {%1, %2};" : "=l"(r) : "f"(a), "f"(b)); return r;
}
__device__ __forceinline__ f2p packv(float2 v) { return pack2(v.x, v.y); }
__device__ __forceinline__ float2 unpackv(f2p v) {
    float2 r; asm("mov.b64 {%0, %1}, %2;" : "=f"(r.x), "=f"(r.y) : "l"(v)); return r;
}
__device__ __forceinline__ f2p padd(f2p a, f2p b) {
    f2p r; asm("add.rn.f32x2 %0, %1, %2;" : "=l"(r) : "l"(a), "l"(b)); return r;
}
// a - b  ==  fma(b, (-1,-1), a)   (fma.rn.f32x2 is the guaranteed packed op)
__device__ __forceinline__ f2p psub(f2p a, f2p b, f2p n1) {
    f2p r; asm("fma.rn.f32x2 %0, %1, %2, %3;" : "=l"(r) : "l"(b), "l"(n1), "l"(a)); return r;
}
// r = a * cn + b   (packed axpy for the epilogue)
__device__ __forceinline__ f2p pfma(f2p a, f2p cn, f2p b) {
    f2p r; asm("fma.rn.f32x2 %0, %1, %2, %3;" : "=l"(r) : "l"(a), "l"(cn), "l"(b)); return r;
}
__device__ __forceinline__ f2p pmi(f2p v) {          // -i*z = (y, -x)
    float2 z = unpackv(v);
    return pack2(z.y, -z.x);
}
__device__ __forceinline__ f2p pw81(f2p v) {         // W8^1 * z
    float2 z = unpackv(v);
    return pack2(SQ2H*(z.x+z.y), SQ2H*(z.y-z.x));
}
__device__ __forceinline__ f2p pw83(f2p v) {         // W8^3 * z
    float2 z = unpackv(v);
    return pack2(SQ2H*(z.y-z.x), -SQ2H*(z.x+z.y));
}

__device__ __forceinline__ float2 cmul(float2 a, float2 b) {
    return make_float2(fmaf(a.x, b.x, -a.y*b.y), fmaf(a.x, b.y, a.y*b.x));
}

// X[k] = sum_n x[n] * W8^{nk}  (radix-2 DIT, packed adds/subs)
__device__ __forceinline__ void dft8p(const f2p* x, f2p* X, const f2p n1) {
    f2p t0 = padd(x[0], x[4]), t1 = psub(x[0], x[4], n1);
    f2p t2 = padd(x[2], x[6]), t3 = psub(x[2], x[6], n1);
    f2p E0 = padd(t0, t2), E2 = psub(t0, t2, n1);
    f2p mt3 = pmi(t3);
    f2p E1 = padd(t1, mt3), E3 = psub(t1, mt3, n1);

    f2p s0 = padd(x[1], x[5]), s1 = psub(x[1], x[5], n1);
    f2p s2 = padd(x[3], x[7]), s3 = psub(x[3], x[7], n1);
    f2p O0 = padd(s0, s2), O2 = psub(s0, s2, n1);
    f2p ms3 = pmi(s3);
    f2p O1 = padd(s1, ms3), O3 = psub(s1, ms3, n1);

    f2p o1 = pw81(O1);
    f2p o2 = pmi(O2);
    f2p o3 = pw83(O3);

    X[0] = padd(E0, O0); X[4] = psub(E0, O0, n1);
    X[1] = padd(E1, o1); X[5] = psub(E1, o1, n1);
    X[2] = padd(E2, o2); X[6] = psub(E2, o2, n1);
    X[3] = padd(E3, o3); X[7] = psub(E3, o3, n1);
}

__global__ __launch_bounds__(128, 9) void ofdm_fused(
    const float* __restrict__ x,
    const float* __restrict__ pilot_raw,
    const float* __restrict__ cof_unit,
    const float* __restrict__ noise_unit,
    float* __restrict__ out)
{
    __shared__ f2p Z[16][8][9];               // padded transpose buffer

    const int tid  = threadIdx.x;
    const int g    = blockIdx.x * 128 + tid;
    const int gsym = g >> 3;                  // 0..53247
    const int lb   = g & 7;
    const int grp  = tid >> 3;
    const int blk  = gsym / NSYM;
    const int sym  = gsym - blk * NSYM;
    const bool isp = (sym == 0);
    // 8-lane group mask: exactly the lanes that share this thread's isp value
    const unsigned gmask = 0xFFu << ((tid & 31) & ~7);

    const f2p n1 = pack2(-1.0f, -1.0f);

    // ---- streaming loads up front ----
    const float2* nb = (const float2*)noise_unit
                     + (size_t)blk * NSYM * MK + sym * MK + KK + lb;
    f2p in[8];
    #pragma unroll
    for (int a = 0; a < 8; a++) in[a] = packv(nb[a * 8]);

    const float2* sp = isp ? ((const float2*)pilot_raw + blk * 64)
                           : ((const float2*)x + ((size_t)blk * SS + (sym - 1)) * 64);
    float2 sv[8];
    #pragma unroll
    for (int d = 0; d < 8; d++) sv[d] = sp[lb + 8 * d];

    // ---- powers p[c] = W64^{lb*c}, log-depth chain from one constant ----
    float2 p1 = c_W8[lb];
    float2 p2 = cmul(p1, p1);
    float2 p3 = cmul(p2, p1);
    float2 p4 = cmul(p2, p2);
    float2 p5 = cmul(p4, p1);
    float2 p6 = cmul(p3, p3);
    float2 p7 = cmul(p4, p3);

    // ---- noise FFT64 stage 1: packed DFT8, scalar twiddles ----
    {
        f2p u[8];
        dft8p(in, u, n1);
        u[1] = packv(cmul(unpackv(u[1]), p1));
        u[2] = packv(cmul(unpackv(u[2]), p2));
        u[3] = packv(cmul(unpackv(u[3]), p3));
        u[4] = packv(cmul(unpackv(u[4]), p4));
        u[5] = packv(cmul(unpackv(u[5]), p5));
        u[6] = packv(cmul(unpackv(u[6]), p6));
        u[7] = packv(cmul(unpackv(u[7]), p7));
        #pragma unroll
        for (int c = 0; c < 8; c++) Z[grp][lb][c] = u[c];
    }

    // ---- H in-thread: Hv[d] = DFT8_l( amp_l*cof_l*W64^{l*lb} ) ----
    f2p Hv[8];
    {
        const float4* cp4 = (const float4*)((const float2*)cof_unit + blk * 8);
        float4 q0 = cp4[0], q1 = cp4[1], q2 = cp4[2], q3 = cp4[3];
        f2p e[8];
        e[0] = pack2(c_amp[0]*q0.x, c_amp[0]*q0.y);
        e[1] = packv(cmul(make_float2(c_amp[1]*q0.z, c_amp[1]*q0.w), p1));
        e[2] = packv(cmul(make_float2(c_amp[2]*q1.x, c_amp[2]*q1.y), p2));
        e[3] = packv(cmul(make_float2(c_amp[3]*q1.z, c_amp[3]*q1.w), p3));
        e[4] = packv(cmul(make_float2(c_amp[4]*q2.x, c_amp[4]*q2.y), p4));
        e[5] = packv(cmul(make_float2(c_amp[5]*q2.z, c_amp[5]*q2.w), p5));
        e[6] = packv(cmul(make_float2(c_amp[6]*q3.x, c_amp[6]*q3.y), p6));
        e[7] = packv(cmul(make_float2(c_amp[7]*q3.z, c_amp[7]*q3.w), p7));
        dft8p(e, Hv, n1);                     // Hv[d] = H[lb + 8d]
    }

    // ---- sym-0 group stores H_true while it's live ----
    if (isp) {
        float2* hq = (float2*)(out + HT_OFF) + blk * 64;
        #pragma unroll
        for (int d = 0; d < 8; d++) hq[lb + 8 * d] = unpackv(Hv[d]);
    }
    if (g == 0) out[NP_OFF] = NOISE_PWR;

    if (isp) {
        // group-local reduction: mask matches exactly the executing lanes
        float pw = 0.f;
        #pragma unroll
        for (int d = 0; d < 8; d++) pw += sv[d].x * sv[d].x + sv[d].y * sv[d].y;
        pw += __shfl_xor_sync(gmask, pw, 1);
        pw += __shfl_xor_sync(gmask, pw, 2);
        pw += __shfl_xor_sync(gmask, pw, 4);
        float scale = 8.0f * rsqrtf(pw);      // sqrt(PWR/2)/sqrt(mean(pilot_raw^2))
        #pragma unroll
        for (int d = 0; d < 8; d++) { sv[d].x *= scale; sv[d].y *= scale; }
    }

    // ---- fold H*sig in place: Hv dies here, before Nf materializes ----
    f2p hs[8];
    #pragma unroll
    for (int d = 0; d < 8; d++) hs[d] = packv(cmul(unpackv(Hv[d]), sv[d]));

    __syncwarp();

    // ---- transpose read + stage 2 (packed) ----
    f2p z[8];
    #pragma unroll
    for (int b = 0; b < 8; b++) z[b] = Z[grp][b][lb];
    f2p Nf[8];
    dft8p(z, Nf, n1);                         // Nf[d] = N[lb + 8d]

    // ---- epilogue: out = (H*sig) + CNOISE * noiseFFT (packed fma) ----
    const f2p cn2 = pack2(CNOISE, CNOISE);
    float2* op = isp ? ((float2*)(out + IP_OFF) + blk * 64)
                     : ((float2*)(out + IS_OFF) + ((size_t)blk * SS + (sym - 1)) * 64);
    #pragma unroll
    for (int d = 0; d < 8; d++) {
        op[lb + 8 * d] = unpackv(pfma(Nf[d], cn2, hs[d]));
    }
}

extern "C" void kernel_launch(void* const* d_in, const int* in_sizes, int n_in,
                              void* d_out, int out_size) {
    const float* x          = (const float*)d_in[0];
    const float* pilot_raw  = (const float*)d_in[1];
    const float* cof_unit   = (const float*)d_in[2];
    const float* noise_unit = (const float*)d_in[3];
    float* out = (float*)d_out;

    ofdm_fused<<<NSYMTOT * 8 / 128, 128>>>(x, pilot_raw, cof_unit, noise_unit, out);
}